// round 1
// baseline (speedup 1.0000x reference)
#include <cuda_runtime.h>

#define BSZ 8192
#define DIM 128

// ---- phase 1: gram partials ----
#define GRAM_BLOCKS 256
#define GRAM_ROWS   32            // rows of Y per block; GRAM_BLOCKS*GRAM_ROWS = BSZ

// ---- phase 3: quadratic forms ----
#define QUAD_BLOCKS 128
#define QUAD_ROWS   64            // rows of X per block; QUAD_BLOCKS*QUAD_ROWS = BSZ

// scratch (static __device__ — no allocations allowed)
__device__ float g_gram_part[GRAM_BLOCKS][3][DIM][DIM];  // ~25 MB
__device__ float g_gram[3][DIM][DIM];                    // Gs, Gt, M
__device__ float g_loss_part[QUAD_BLOCKS];

// ============================================================================
// Kernel 1: per-block partial Grams of row-normalized ys/yt.
//   Gs = Ys^T Ys, Gt = Yt^T Yt, M = Ys^T Yt  (all 128x128, K-chunked)
// 256 threads; 16x16 thread grid, 8x8 register tile of the 128x128 output.
// ============================================================================
__device__ __forceinline__ void load_norm_rows32(const float* __restrict__ src,
                                                 float (*dst)[DIM], int row0, int tid) {
    // 32 rows, 256 threads -> 8 threads/row, 16 floats (4x float4) each
    int r = tid >> 3;
    int part = tid & 7;
    const float4* s = reinterpret_cast<const float4*>(src + (size_t)(row0 + r) * DIM) + part * 4;
    float4 v[4];
    float ss = 0.f;
#pragma unroll
    for (int i = 0; i < 4; i++) {
        v[i] = s[i];
        ss += v[i].x * v[i].x + v[i].y * v[i].y + v[i].z * v[i].z + v[i].w * v[i].w;
    }
    ss += __shfl_xor_sync(0xffffffffu, ss, 1);
    ss += __shfl_xor_sync(0xffffffffu, ss, 2);
    ss += __shfl_xor_sync(0xffffffffu, ss, 4);
    float inv = rsqrtf(fmaxf(ss, 1e-24f));
    float4* d = reinterpret_cast<float4*>(&dst[r][0]) + part * 4;
#pragma unroll
    for (int i = 0; i < 4; i++) {
        v[i].x *= inv; v[i].y *= inv; v[i].z *= inv; v[i].w *= inv;
        d[i] = v[i];
    }
}

__global__ void __launch_bounds__(256) gram_kernel(const float* __restrict__ ys,
                                                   const float* __restrict__ yt) {
    __shared__ float sYs[GRAM_ROWS][DIM];
    __shared__ float sYt[GRAM_ROWS][DIM];
    const int tid = threadIdx.x;
    const int row0 = blockIdx.x * GRAM_ROWS;

    load_norm_rows32(ys, sYs, row0, tid);
    load_norm_rows32(yt, sYt, row0, tid);
    __syncthreads();

    const int tx = tid & 15;   // column tile
    const int ty = tid >> 4;   // row tile

#pragma unroll 1
    for (int m = 0; m < 3; m++) {
        const float (*A)[DIM] = (m == 1) ? sYt : sYs;   // left index of G
        const float (*B)[DIM] = (m == 0) ? sYs : sYt;   // right index of G
        float acc[8][8];
#pragma unroll
        for (int u = 0; u < 8; u++)
#pragma unroll
            for (int v = 0; v < 8; v++) acc[u][v] = 0.f;

#pragma unroll 4
        for (int k = 0; k < GRAM_ROWS; k++) {
            float4 a0 = *(const float4*)&A[k][ty * 8];
            float4 a1 = *(const float4*)&A[k][ty * 8 + 4];
            float4 b0 = *(const float4*)&B[k][tx * 8];
            float4 b1 = *(const float4*)&B[k][tx * 8 + 4];
            float av[8] = {a0.x, a0.y, a0.z, a0.w, a1.x, a1.y, a1.z, a1.w};
            float bv[8] = {b0.x, b0.y, b0.z, b0.w, b1.x, b1.y, b1.z, b1.w};
#pragma unroll
            for (int u = 0; u < 8; u++)
#pragma unroll
                for (int v = 0; v < 8; v++)
                    acc[u][v] = fmaf(av[u], bv[v], acc[u][v]);
        }

        float* out = &g_gram_part[blockIdx.x][m][0][0];
#pragma unroll
        for (int u = 0; u < 8; u++) {
            int a = ty * 8 + u;
            *(float4*)&out[a * DIM + tx * 8] =
                make_float4(acc[u][0], acc[u][1], acc[u][2], acc[u][3]);
            *(float4*)&out[a * DIM + tx * 8 + 4] =
                make_float4(acc[u][4], acc[u][5], acc[u][6], acc[u][7]);
        }
    }
}

// ============================================================================
// Kernel 2: reduce gram partials (fixed order -> deterministic)
// ============================================================================
__global__ void reduce_gram_kernel() {
    int e = blockIdx.x * blockDim.x + threadIdx.x;   // 0 .. 3*128*128-1
    const float* base = &g_gram_part[0][0][0][0];
    float s = 0.f;
#pragma unroll 8
    for (int p = 0; p < GRAM_BLOCKS; p++)
        s += base[(size_t)p * (3 * DIM * DIM) + e];
    (&g_gram[0][0][0])[e] = s;
}

// ============================================================================
// Kernel 3: quadratic forms per X row + per-block partial sum of cosines.
//   A_i = xs_i^T Gs xs_i, B_i = xt_i^T Gt xt_i, C_i = xs_i^T M xt_i
// 64 rows/block, 256 threads, G tile in dynamic shared (needs >48KB attr).
// ============================================================================
#define QUAD_SMEM_FLOATS (2 * QUAD_ROWS * DIM + DIM * DIM + 3 * QUAD_ROWS + QUAD_ROWS)
#define QUAD_SMEM_BYTES  (QUAD_SMEM_FLOATS * 4)

__global__ void __launch_bounds__(256) quad_kernel(const float* __restrict__ xs,
                                                   const float* __restrict__ xt) {
    extern __shared__ float smq[];
    float (*sXs)[DIM] = (float(*)[DIM])smq;                               // 64x128
    float (*sXt)[DIM] = (float(*)[DIM])(smq + QUAD_ROWS * DIM);           // 64x128
    float (*sG)[DIM]  = (float(*)[DIM])(smq + 2 * QUAD_ROWS * DIM);       // 128x128
    float* sABC = smq + 2 * QUAD_ROWS * DIM + DIM * DIM;                  // [3][64]
    float* sCos = sABC + 3 * QUAD_ROWS;                                   // [64]

    const int tid = threadIdx.x;
    const int row0 = blockIdx.x * QUAD_ROWS;

    // load + normalize 64 rows of xs and xt: 4 threads/row, 32 floats each
    {
        int r = tid >> 2;
        int part = tid & 3;
#pragma unroll 1
        for (int which = 0; which < 2; which++) {
            const float* src = which ? xt : xs;
            float (*dst)[DIM] = which ? sXt : sXs;
            const float4* s = reinterpret_cast<const float4*>(src + (size_t)(row0 + r) * DIM) + part * 8;
            float4 v[8];
            float ss = 0.f;
#pragma unroll
            for (int i = 0; i < 8; i++) {
                v[i] = s[i];
                ss += v[i].x * v[i].x + v[i].y * v[i].y + v[i].z * v[i].z + v[i].w * v[i].w;
            }
            ss += __shfl_xor_sync(0xffffffffu, ss, 1);
            ss += __shfl_xor_sync(0xffffffffu, ss, 2);
            float inv = rsqrtf(fmaxf(ss, 1e-24f));
            float4* d = reinterpret_cast<float4*>(&dst[r][0]) + part * 8;
#pragma unroll
            for (int i = 0; i < 8; i++) {
                v[i].x *= inv; v[i].y *= inv; v[i].z *= inv; v[i].w *= inv;
                d[i] = v[i];
            }
        }
    }

    const int tx = tid & 15;
    const int ty = tid >> 4;

#pragma unroll 1
    for (int m = 0; m < 3; m++) {
        __syncthreads();   // previous iter's sG reads done (also covers X-load on m=0)
        // stage G[m] into shared: 16384 floats / 256 threads = 16 float4 each
        {
            const float4* gsrc = (const float4*)&g_gram[m][0][0];
            float4* gdst = (float4*)&sG[0][0];
#pragma unroll
            for (int i = 0; i < 16; i++)
                gdst[tid + i * 256] = gsrc[tid + i * 256];
        }
        __syncthreads();

        const float (*Xa)[DIM] = (m == 1) ? sXt : sXs;   // left vector
        const float (*Xb)[DIM] = (m == 0) ? sXs : sXt;   // right vector

        float acc[4][8];
#pragma unroll
        for (int u = 0; u < 4; u++)
#pragma unroll
            for (int v = 0; v < 8; v++) acc[u][v] = 0.f;

        for (int k = 0; k < DIM; k += 4) {
            float4 av[4];
#pragma unroll
            for (int u = 0; u < 4; u++)
                av[u] = *(const float4*)&Xa[ty * 4 + u][k];
#pragma unroll
            for (int kk = 0; kk < 4; kk++) {
                float4 g0 = *(const float4*)&sG[k + kk][tx * 8];
                float4 g1 = *(const float4*)&sG[k + kk][tx * 8 + 4];
                float gv[8] = {g0.x, g0.y, g0.z, g0.w, g1.x, g1.y, g1.z, g1.w};
#pragma unroll
                for (int u = 0; u < 4; u++) {
                    float a = (kk == 0) ? av[u].x : (kk == 1) ? av[u].y
                            : (kk == 2) ? av[u].z : av[u].w;
#pragma unroll
                    for (int v = 0; v < 8; v++)
                        acc[u][v] = fmaf(a, gv[v], acc[u][v]);
                }
            }
        }

        // epilogue: pr[u] = sum_v acc[u][v] * Xb[row][tx*8+v]; reduce over tx halves
        float pr[4];
#pragma unroll
        for (int u = 0; u < 4; u++) {
            float4 x0 = *(const float4*)&Xb[ty * 4 + u][tx * 8];
            float4 x1 = *(const float4*)&Xb[ty * 4 + u][tx * 8 + 4];
            pr[u] = acc[u][0] * x0.x + acc[u][1] * x0.y + acc[u][2] * x0.z + acc[u][3] * x0.w
                  + acc[u][4] * x1.x + acc[u][5] * x1.y + acc[u][6] * x1.z + acc[u][7] * x1.w;
        }
#pragma unroll
        for (int off = 1; off < 16; off <<= 1)
#pragma unroll
            for (int u = 0; u < 4; u++)
                pr[u] += __shfl_xor_sync(0xffffffffu, pr[u], off);
        if (tx == 0) {
#pragma unroll
            for (int u = 0; u < 4; u++)
                sABC[m * QUAD_ROWS + ty * 4 + u] = pr[u];
        }
    }
    __syncthreads();

    if (tid < QUAD_ROWS) {
        float A = sABC[tid];
        float B = sABC[QUAD_ROWS + tid];
        float C = sABC[2 * QUAD_ROWS + tid];
        sCos[tid] = C * rsqrtf(fmaxf(A * B, 1e-30f));
    }
    __syncthreads();
    if (tid == 0) {
        float s = 0.f;
#pragma unroll 8
        for (int i = 0; i < QUAD_ROWS; i++) s += sCos[i];
        g_loss_part[blockIdx.x] = s;
    }
}

// ============================================================================
// Kernel 4: final deterministic reduction + loss
//   loss = (2b - 2*sum_i cos_i) / b^2      (temperature cancels exactly)
// ============================================================================
__global__ void final_kernel(float* __restrict__ out) {
    if (threadIdx.x == 0 && blockIdx.x == 0) {
        float s = 0.f;
#pragma unroll 8
        for (int i = 0; i < QUAD_BLOCKS; i++) s += g_loss_part[i];
        const float b = (float)BSZ;
        out[0] = (2.f * b - 2.f * s) / (b * b);
    }
}

// ============================================================================
extern "C" void kernel_launch(void* const* d_in, const int* in_sizes, int n_in,
                              void* d_out, int out_size) {
    (void)in_sizes; (void)n_in; (void)out_size;
    const float* zxs = (const float*)d_in[0];
    const float* zys = (const float*)d_in[1];
    const float* zxt = (const float*)d_in[2];
    const float* zyt = (const float*)d_in[3];
    // d_in[4] = temperature: mathematically cancels under row-normalization.

    cudaFuncSetAttribute(quad_kernel, cudaFuncAttributeMaxDynamicSharedMemorySize,
                         QUAD_SMEM_BYTES);

    gram_kernel<<<GRAM_BLOCKS, 256>>>(zys, zyt);
    reduce_gram_kernel<<<(3 * DIM * DIM) / 256, 256>>>();
    quad_kernel<<<QUAD_BLOCKS, 256, QUAD_SMEM_BYTES>>>(zxs, zxt);
    final_kernel<<<1, 1>>>((float*)d_out);
}

// round 2
// speedup vs baseline: 1.1304x; 1.1304x over previous
#include <cuda_runtime.h>

#define BSZ 8192
#define DIM 128

// ---- phase 1: gram partials ----
#define GRAM_BLOCKS 128
#define GRAM_ROWS   64            // GRAM_BLOCKS*GRAM_ROWS = BSZ
#define GRAM_SMEM_BYTES (2 * GRAM_ROWS * DIM * 4)   // 64 KB

// ---- phase 3: quadratic forms ----
#define QUAD_BLOCKS 128
#define QUAD_ROWS   64

// scratch (static __device__ — no allocations allowed)
__device__ float g_gram_part[GRAM_BLOCKS][3][DIM][DIM];  // ~25 MB
__device__ float g_gram[3][DIM][DIM];                    // Gs, Gt, M
__device__ float g_loss_part[QUAD_BLOCKS];

// ---------------------------------------------------------------------------
// f32x2 packed-FMA helpers (FFMA2 — only reachable via PTX fma.rn.f32x2)
// ---------------------------------------------------------------------------
typedef unsigned long long u64;

__device__ __forceinline__ u64 pack2(float lo, float hi) {
    u64 r; asm("mov.b64 %0, {%1, %2};" : "=l"(r) : "f"(lo), "f"(hi)); return r;
}
__device__ __forceinline__ void unpack2(u64 v, float& lo, float& hi) {
    asm("mov.b64 {%0, %1}, %2;" : "=f"(lo), "=f"(hi) : "l"(v));
}
__device__ __forceinline__ u64 fma2(u64 a, u64 b, u64 c) {
    u64 d; asm("fma.rn.f32x2 %0, %1, %2, %3;" : "=l"(d) : "l"(a), "l"(b), "l"(c));
    return d;
}

// ---------------------------------------------------------------------------
// load + row-normalize 64 rows of [row0..row0+64) x 128 into shared.
// 256 threads: 4 threads/row, 32 floats (8 float4) each.
// ---------------------------------------------------------------------------
__device__ __forceinline__ void load_norm_rows64(const float* __restrict__ src,
                                                 float* __restrict__ dst,
                                                 int row0, int tid) {
    int r = tid >> 2;
    int part = tid & 3;
    const float4* s = reinterpret_cast<const float4*>(src + (size_t)(row0 + r) * DIM) + part * 8;
    float4 v[8];
    float ss = 0.f;
#pragma unroll
    for (int i = 0; i < 8; i++) {
        v[i] = s[i];
        ss += v[i].x * v[i].x + v[i].y * v[i].y + v[i].z * v[i].z + v[i].w * v[i].w;
    }
    ss += __shfl_xor_sync(0xffffffffu, ss, 1);
    ss += __shfl_xor_sync(0xffffffffu, ss, 2);
    float inv = rsqrtf(fmaxf(ss, 1e-24f));
    float4* d = reinterpret_cast<float4*>(dst + (size_t)r * DIM) + part * 8;
#pragma unroll
    for (int i = 0; i < 8; i++) {
        v[i].x *= inv; v[i].y *= inv; v[i].z *= inv; v[i].w *= inv;
        d[i] = v[i];
    }
}

// ============================================================================
// Kernel 1: per-block partial Grams of row-normalized ys/yt (K-chunk = 64).
//   Gs = Ys^T Ys, Gt = Yt^T Yt, M = Ys^T Yt  (all 128x128)
// 256 threads; 16x16 thread grid, 8x8 register tile, f32x2 packed FMA.
// ============================================================================
__global__ void __launch_bounds__(256) gram_kernel(const float* __restrict__ ys,
                                                   const float* __restrict__ yt) {
    extern __shared__ float smg[];
    float* sYs = smg;                       // [64][128]
    float* sYt = smg + GRAM_ROWS * DIM;     // [64][128]

    const int tid = threadIdx.x;
    const int row0 = blockIdx.x * GRAM_ROWS;

    load_norm_rows64(ys, sYs, row0, tid);
    load_norm_rows64(yt, sYt, row0, tid);
    __syncthreads();

    const int tx = tid & 15;   // column tile (8 cols)
    const int ty = tid >> 4;   // row tile    (8 rows)

#pragma unroll 1
    for (int m = 0; m < 3; m++) {
        const float* A = (m == 1) ? sYt : sYs;   // left index of G
        const float* B = (m == 0) ? sYs : sYt;   // right index of G

        u64 acc2[8][4];
#pragma unroll
        for (int u = 0; u < 8; u++)
#pragma unroll
            for (int v = 0; v < 4; v++) acc2[u][v] = 0ull;

#pragma unroll 4
        for (int k = 0; k < GRAM_ROWS; k++) {
            float4 a0 = *(const float4*)(A + k * DIM + ty * 8);
            float4 a1 = *(const float4*)(A + k * DIM + ty * 8 + 4);
            float4 b0 = *(const float4*)(B + k * DIM + tx * 8);
            float4 b1 = *(const float4*)(B + k * DIM + tx * 8 + 4);
            u64 bp[4] = {pack2(b0.x, b0.y), pack2(b0.z, b0.w),
                         pack2(b1.x, b1.y), pack2(b1.z, b1.w)};
            float av[8] = {a0.x, a0.y, a0.z, a0.w, a1.x, a1.y, a1.z, a1.w};
#pragma unroll
            for (int u = 0; u < 8; u++) {
                u64 as = pack2(av[u], av[u]);
#pragma unroll
                for (int v = 0; v < 4; v++)
                    acc2[u][v] = fma2(as, bp[v], acc2[u][v]);
            }
        }

        float* out = &g_gram_part[blockIdx.x][m][0][0];
#pragma unroll
        for (int u = 0; u < 8; u++) {
            float c[8];
#pragma unroll
            for (int v = 0; v < 4; v++) unpack2(acc2[u][v], c[2 * v], c[2 * v + 1]);
            int a = ty * 8 + u;
            *(float4*)&out[a * DIM + tx * 8]     = make_float4(c[0], c[1], c[2], c[3]);
            *(float4*)&out[a * DIM + tx * 8 + 4] = make_float4(c[4], c[5], c[6], c[7]);
        }
    }
}

// ============================================================================
// Kernel 2: reduce gram partials (fixed order -> deterministic)
// ============================================================================
__global__ void reduce_gram_kernel() {
    int e = blockIdx.x * blockDim.x + threadIdx.x;   // 0 .. 3*128*128-1
    const float* base = &g_gram_part[0][0][0][0];
    float s = 0.f;
#pragma unroll 16
    for (int p = 0; p < GRAM_BLOCKS; p++)
        s += base[(size_t)p * (3 * DIM * DIM) + e];
    (&g_gram[0][0][0])[e] = s;
}

// ============================================================================
// Kernel 3: quadratic forms per X row + per-block partial sum of cosines.
//   A_i = xs_i^T Gs xs_i, B_i = xt_i^T Gt xt_i, C_i = xs_i^T M xt_i
// 64 rows/block, 256 threads, G tile in dynamic shared, f32x2 packed FMA.
// ============================================================================
#define QUAD_SMEM_FLOATS (2 * QUAD_ROWS * DIM + DIM * DIM + 3 * QUAD_ROWS + QUAD_ROWS)
#define QUAD_SMEM_BYTES  (QUAD_SMEM_FLOATS * 4)

__global__ void __launch_bounds__(256) quad_kernel(const float* __restrict__ xs,
                                                   const float* __restrict__ xt) {
    extern __shared__ float smq[];
    float* sXs = smq;                                    // [64][128]
    float* sXt = smq + QUAD_ROWS * DIM;                  // [64][128]
    float* sG  = smq + 2 * QUAD_ROWS * DIM;              // [128][128]
    float* sABC = smq + 2 * QUAD_ROWS * DIM + DIM * DIM; // [3][64]
    float* sCos = sABC + 3 * QUAD_ROWS;                  // [64]

    const int tid = threadIdx.x;
    const int row0 = blockIdx.x * QUAD_ROWS;

    load_norm_rows64(xs, sXs, row0, tid);
    load_norm_rows64(xt, sXt, row0, tid);

    const int tx = tid & 15;
    const int ty = tid >> 4;

#pragma unroll 1
    for (int m = 0; m < 3; m++) {
        __syncthreads();   // prior sG reads done (covers X-load on m=0)
        // stage G[m]: 16384 floats / 256 threads = 16 float4 each
        {
            const float4* gsrc = (const float4*)&g_gram[m][0][0];
            float4* gdst = (float4*)sG;
#pragma unroll
            for (int i = 0; i < 16; i++)
                gdst[tid + i * 256] = gsrc[tid + i * 256];
        }
        __syncthreads();

        const float* Xa = (m == 1) ? sXt : sXs;   // left vector
        const float* Xb = (m == 0) ? sXs : sXt;   // right vector

        u64 acc2[4][4];
#pragma unroll
        for (int u = 0; u < 4; u++)
#pragma unroll
            for (int v = 0; v < 4; v++) acc2[u][v] = 0ull;

        for (int k = 0; k < DIM; k += 4) {
            float4 av[4];
#pragma unroll
            for (int u = 0; u < 4; u++)
                av[u] = *(const float4*)(Xa + (ty * 4 + u) * DIM + k);
#pragma unroll
            for (int kk = 0; kk < 4; kk++) {
                float4 g0 = *(const float4*)(sG + (k + kk) * DIM + tx * 8);
                float4 g1 = *(const float4*)(sG + (k + kk) * DIM + tx * 8 + 4);
                u64 gp[4] = {pack2(g0.x, g0.y), pack2(g0.z, g0.w),
                             pack2(g1.x, g1.y), pack2(g1.z, g1.w)};
#pragma unroll
                for (int u = 0; u < 4; u++) {
                    float a = (kk == 0) ? av[u].x : (kk == 1) ? av[u].y
                            : (kk == 2) ? av[u].z : av[u].w;
                    u64 as = pack2(a, a);
#pragma unroll
                    for (int v = 0; v < 4; v++)
                        acc2[u][v] = fma2(as, gp[v], acc2[u][v]);
                }
            }
        }

        // epilogue: pr[u] = sum_v acc[u][v] * Xb[row][tx*8+v]; reduce across tx
        float pr[4];
#pragma unroll
        for (int u = 0; u < 4; u++) {
            float c[8];
#pragma unroll
            for (int v = 0; v < 4; v++) unpack2(acc2[u][v], c[2 * v], c[2 * v + 1]);
            float4 x0 = *(const float4*)(Xb + (ty * 4 + u) * DIM + tx * 8);
            float4 x1 = *(const float4*)(Xb + (ty * 4 + u) * DIM + tx * 8 + 4);
            pr[u] = c[0] * x0.x + c[1] * x0.y + c[2] * x0.z + c[3] * x0.w
                  + c[4] * x1.x + c[5] * x1.y + c[6] * x1.z + c[7] * x1.w;
        }
#pragma unroll
        for (int off = 1; off < 16; off <<= 1)
#pragma unroll
            for (int u = 0; u < 4; u++)
                pr[u] += __shfl_xor_sync(0xffffffffu, pr[u], off);
        if (tx == 0) {
#pragma unroll
            for (int u = 0; u < 4; u++)
                sABC[m * QUAD_ROWS + ty * 4 + u] = pr[u];
        }
    }
    __syncthreads();

    if (tid < QUAD_ROWS) {
        float A = sABC[tid];
        float B = sABC[QUAD_ROWS + tid];
        float C = sABC[2 * QUAD_ROWS + tid];
        sCos[tid] = C * rsqrtf(fmaxf(A * B, 1e-30f));
    }
    __syncthreads();
    if (tid == 0) {
        float s = 0.f;
#pragma unroll 8
        for (int i = 0; i < QUAD_ROWS; i++) s += sCos[i];
        g_loss_part[blockIdx.x] = s;
    }
}

// ============================================================================
// Kernel 4: final deterministic reduction + loss (parallel, fixed tree order)
//   loss = (2b - 2*sum_i cos_i) / b^2      (temperature cancels exactly)
// ============================================================================
__global__ void __launch_bounds__(QUAD_BLOCKS) final_kernel(float* __restrict__ out) {
    __shared__ float w[QUAD_BLOCKS / 32];
    int tid = threadIdx.x;
    float v = g_loss_part[tid];
#pragma unroll
    for (int off = 16; off > 0; off >>= 1)
        v += __shfl_xor_sync(0xffffffffu, v, off);
    if ((tid & 31) == 0) w[tid >> 5] = v;
    __syncthreads();
    if (tid == 0) {
        float s = 0.f;
#pragma unroll
        for (int i = 0; i < QUAD_BLOCKS / 32; i++) s += w[i];
        const float b = (float)BSZ;
        out[0] = (2.f * b - 2.f * s) / (b * b);
    }
}

// ============================================================================
extern "C" void kernel_launch(void* const* d_in, const int* in_sizes, int n_in,
                              void* d_out, int out_size) {
    (void)in_sizes; (void)n_in; (void)out_size;
    const float* zxs = (const float*)d_in[0];
    const float* zys = (const float*)d_in[1];
    const float* zxt = (const float*)d_in[2];
    const float* zyt = (const float*)d_in[3];
    // d_in[4] = temperature: mathematically cancels under row-normalization.

    cudaFuncSetAttribute(gram_kernel, cudaFuncAttributeMaxDynamicSharedMemorySize,
                         GRAM_SMEM_BYTES);
    cudaFuncSetAttribute(quad_kernel, cudaFuncAttributeMaxDynamicSharedMemorySize,
                         QUAD_SMEM_BYTES);

    gram_kernel<<<GRAM_BLOCKS, 256, GRAM_SMEM_BYTES>>>(zys, zyt);
    reduce_gram_kernel<<<(3 * DIM * DIM) / 256, 256>>>();
    quad_kernel<<<QUAD_BLOCKS, 256, QUAD_SMEM_BYTES>>>(zxs, zxt);
    final_kernel<<<1, QUAD_BLOCKS>>>((float*)d_out);
}

// round 4
// speedup vs baseline: 1.7278x; 1.5284x over previous
#include <cuda_runtime.h>
#include <cstdint>

#define BSZ 8192
#define DIM 128

// ---- phase 1: gram via mma.sync tf32 (HMMA legacy path; tcgen05 PTX is
// ---- rejected at the harness's compute_103 target) ----
#define GRAM_CTAS 64
#define GRAM_K    128                 // rows per CTA
#define YP 136                        // Y pitch (floats): 136%32==8 -> conflict-free frags
#define GRAM_SMEM_BYTES (2 * GRAM_K * YP * 4)   // 139264

// ---- phase 3: quadratic forms via mma.sync tf32 ----
#define QUAD_BLOCKS 128
#define QUAD_ROWS   64
#define XP 132                        // X pitch: 132%32==4 -> conflict-free A frags
#define GP 136                        // G pitch
#define QUAD_SMEM_BYTES (2 * QUAD_ROWS * XP * 4 + DIM * GP * 4 + 3 * 2 * QUAD_ROWS * 4 + QUAD_ROWS * 4)

__device__ float g_gram_part[GRAM_CTAS][3][DIM][DIM];   // ~12.6 MB
__device__ float g_gram[3][DIM][DIM];
__device__ float g_loss_part[QUAD_BLOCKS];

// ---------------------------------------------------------------------------
__device__ __forceinline__ uint32_t to_tf32(float f) {
    uint32_t r;
    asm("cvt.rn.tf32.f32 %0, %1;" : "=r"(r) : "f"(f));
    return r;
}

// D(16x8) += A(16x8) * B(8x8), tf32 inputs, f32 accum. sm_80 baseline feature.
__device__ __forceinline__ void mma_tf32(float* d, const uint32_t* a, uint32_t b0, uint32_t b1) {
    asm volatile(
        "mma.sync.aligned.m16n8k8.row.col.f32.tf32.tf32.f32 "
        "{%0,%1,%2,%3}, {%4,%5,%6,%7}, {%8,%9}, {%0,%1,%2,%3};"
        : "+f"(d[0]), "+f"(d[1]), "+f"(d[2]), "+f"(d[3])
        : "r"(a[0]), "r"(a[1]), "r"(a[2]), "r"(a[3]), "r"(b0), "r"(b1));
}

// ============================================================================
// Kernel 1: gram partials.
//   Per CTA: normalize 128 rows of ys/yt (fp32), store tf32 into shared
//   [128][YP]; 8 warps each compute a 16x128 strip of G via mma.sync;
//   3 chains: Gs=Ys^T Ys, Gt=Yt^T Yt, M=Ys^T Yt.
//   Fragment loads (row.col, m16n8k8):
//     a0 = A[m0+gid][k0+tg] = Y[k0+tg][m0+gid]      (gid=lane>>2, tg=lane&3)
//     b0 = B[k0+tg][n0+gid] = Y[k0+tg][n0+gid]
// ============================================================================
__global__ void __launch_bounds__(256) gram_kernel(const float* __restrict__ ys,
                                                   const float* __restrict__ yt) {
    extern __shared__ uint32_t smg[];
    uint32_t* sY[2] = {smg, smg + GRAM_K * YP};

    const int tid  = threadIdx.x;
    const int wid  = tid >> 5;
    const int lane = tid & 31;
    const int gid  = lane >> 2;
    const int tg   = lane & 3;
    const int row0 = blockIdx.x * GRAM_K;

    // load + normalize: 2 threads/row, 64 floats each; store tf32 bits
#pragma unroll 1
    for (int which = 0; which < 2; which++) {
        const float* src = which ? yt : ys;
        int r = tid >> 1, part = tid & 1;
        const float4* s = (const float4*)(src + (size_t)(row0 + r) * DIM) + part * 16;
        float4 v[16];
        float ss = 0.f;
#pragma unroll
        for (int i = 0; i < 16; i++) {
            v[i] = s[i];
            ss += v[i].x * v[i].x + v[i].y * v[i].y + v[i].z * v[i].z + v[i].w * v[i].w;
        }
        ss += __shfl_xor_sync(0xffffffffu, ss, 1);
        float inv = rsqrtf(fmaxf(ss, 1e-24f));
        uint32_t* d = sY[which] + (size_t)r * YP + part * 64;
#pragma unroll
        for (int i = 0; i < 16; i++) {
            uint4 t;
            t.x = to_tf32(v[i].x * inv);
            t.y = to_tf32(v[i].y * inv);
            t.z = to_tf32(v[i].z * inv);
            t.w = to_tf32(v[i].w * inv);
            *(uint4*)(d + i * 4) = t;
        }
    }
    __syncthreads();

    const int m0 = wid * 16;

#pragma unroll 1
    for (int m = 0; m < 3; m++) {
        const uint32_t* Ya = sY[m == 1 ? 1 : 0];
        const uint32_t* Yb = sY[m == 0 ? 0 : 1];

        float acc[16][4];
#pragma unroll
        for (int t = 0; t < 16; t++)
#pragma unroll
            for (int j = 0; j < 4; j++) acc[t][j] = 0.f;

#pragma unroll 2
        for (int k0 = 0; k0 < GRAM_K; k0 += 8) {
            uint32_t a[4];
            a[0] = Ya[(k0 + tg) * YP + m0 + gid];
            a[1] = Ya[(k0 + tg) * YP + m0 + 8 + gid];
            a[2] = Ya[(k0 + 4 + tg) * YP + m0 + gid];
            a[3] = Ya[(k0 + 4 + tg) * YP + m0 + 8 + gid];
#pragma unroll
            for (int t = 0; t < 16; t++) {
                uint32_t b0 = Yb[(k0 + tg) * YP + t * 8 + gid];
                uint32_t b1 = Yb[(k0 + 4 + tg) * YP + t * 8 + gid];
                mma_tf32(acc[t], a, b0, b1);
            }
        }

        float* dst = &g_gram_part[blockIdx.x][m][0][0];
        int r1 = m0 + gid, r2 = m0 + 8 + gid;
#pragma unroll
        for (int t = 0; t < 16; t++) {
            *(float2*)(dst + r1 * DIM + t * 8 + 2 * tg) = make_float2(acc[t][0], acc[t][1]);
            *(float2*)(dst + r2 * DIM + t * 8 + 2 * tg) = make_float2(acc[t][2], acc[t][3]);
        }
    }
}

// ============================================================================
// Kernel 2: reduce gram partials (fixed order -> deterministic)
// ============================================================================
__global__ void reduce_gram_kernel() {
    int e = blockIdx.x * blockDim.x + threadIdx.x;   // 0 .. 3*128*128-1
    const float* base = &g_gram_part[0][0][0][0];
    float s = 0.f;
#pragma unroll 16
    for (int p = 0; p < GRAM_CTAS; p++)
        s += base[(size_t)p * (3 * DIM * DIM) + e];
    (&g_gram[0][0][0])[e] = s;
}

// ============================================================================
// Kernel 3: quadratic forms via mma.sync.
//   Per block: 64 rows. P = Xa @ G (mma, tf32), pr_i = <P_i, Xb_i> (fp32),
//   cos_i = C_i / sqrt(A_i B_i), partial sum -> g_loss_part.
//   Warp w: m-tile (w&3)*16, n-half (w>>2)*64 (8 n-tiles).
// ============================================================================
__global__ void __launch_bounds__(256) quad_kernel(const float* __restrict__ xs,
                                                   const float* __restrict__ xt) {
    extern __shared__ float smq[];
    float* sX[2] = {smq, smq + QUAD_ROWS * XP};                 // fp32, pitch 132
    uint32_t* sG = (uint32_t*)(smq + 2 * QUAD_ROWS * XP);       // tf32, pitch 136
    float* sP = smq + 2 * QUAD_ROWS * XP + DIM * GP;            // [3][2][64]
    float* sCos = sP + 3 * 2 * QUAD_ROWS;                       // [64]

    const int tid  = threadIdx.x;
    const int wid  = tid >> 5;
    const int lane = tid & 31;
    const int gid  = lane >> 2;
    const int tg   = lane & 3;
    const int row0 = blockIdx.x * QUAD_ROWS;

    // load + normalize 64 rows of xs/xt: 4 threads/row, 32 floats each (fp32)
#pragma unroll 1
    for (int which = 0; which < 2; which++) {
        const float* src = which ? xt : xs;
        int r = tid >> 2, part = tid & 3;
        const float4* s = (const float4*)(src + (size_t)(row0 + r) * DIM) + part * 8;
        float4 v[8];
        float ss = 0.f;
#pragma unroll
        for (int i = 0; i < 8; i++) {
            v[i] = s[i];
            ss += v[i].x * v[i].x + v[i].y * v[i].y + v[i].z * v[i].z + v[i].w * v[i].w;
        }
        ss += __shfl_xor_sync(0xffffffffu, ss, 1);
        ss += __shfl_xor_sync(0xffffffffu, ss, 2);
        float inv = rsqrtf(fmaxf(ss, 1e-24f));
        float4* d = (float4*)(sX[which] + (size_t)r * XP + part * 32);
#pragma unroll
        for (int i = 0; i < 8; i++) {
            v[i].x *= inv; v[i].y *= inv; v[i].z *= inv; v[i].w *= inv;
            d[i] = v[i];
        }
    }

    const int m0 = (wid & 3) * 16;
    const int nh = wid >> 2;          // n half: 0 or 1

#pragma unroll 1
    for (int m = 0; m < 3; m++) {
        __syncthreads();   // X writes visible (m=0) / prior-mat sG reads done
        // stage G[m] as tf32, pitch GP: 256 threads x 16 float4
        {
            const float4* gsrc = (const float4*)&g_gram[m][0][0];
#pragma unroll
            for (int i = 0; i < 16; i++) {
                int idx = tid + i * 256;          // float4 index
                float4 g = gsrc[idx];
                int rrow = idx >> 5;              // /32 float4s per row
                int rcol = (idx & 31) * 4;
                uint4 t;
                t.x = to_tf32(g.x); t.y = to_tf32(g.y);
                t.z = to_tf32(g.z); t.w = to_tf32(g.w);
                *(uint4*)(sG + rrow * GP + rcol) = t;
            }
        }
        __syncthreads();

        const float* Xa = sX[m == 1 ? 1 : 0];
        const float* Xb = sX[m == 0 ? 0 : 1];

        float acc[8][4];
#pragma unroll
        for (int t = 0; t < 8; t++)
#pragma unroll
            for (int j = 0; j < 4; j++) acc[t][j] = 0.f;

#pragma unroll 2
        for (int k0 = 0; k0 < DIM; k0 += 8) {
            uint32_t a[4];
            a[0] = to_tf32(Xa[(m0 + gid) * XP + k0 + tg]);
            a[1] = to_tf32(Xa[(m0 + 8 + gid) * XP + k0 + tg]);
            a[2] = to_tf32(Xa[(m0 + gid) * XP + k0 + 4 + tg]);
            a[3] = to_tf32(Xa[(m0 + 8 + gid) * XP + k0 + 4 + tg]);
#pragma unroll
            for (int t = 0; t < 8; t++) {
                int n0 = nh * 64 + t * 8;
                uint32_t b0 = sG[(k0 + tg) * GP + n0 + gid];
                uint32_t b1 = sG[(k0 + 4 + tg) * GP + n0 + gid];
                mma_tf32(acc[t], a, b0, b1);
            }
        }

        // epilogue: dot with Xb rows, reduce over tg lanes
        float p1 = 0.f, p2 = 0.f;
#pragma unroll
        for (int t = 0; t < 8; t++) {
            int n0 = nh * 64 + t * 8;
            float2 x1 = *(const float2*)(Xb + (m0 + gid) * XP + n0 + 2 * tg);
            float2 x2 = *(const float2*)(Xb + (m0 + 8 + gid) * XP + n0 + 2 * tg);
            p1 += acc[t][0] * x1.x + acc[t][1] * x1.y;
            p2 += acc[t][2] * x2.x + acc[t][3] * x2.y;
        }
        p1 += __shfl_xor_sync(0xffffffffu, p1, 1);
        p1 += __shfl_xor_sync(0xffffffffu, p1, 2);
        p2 += __shfl_xor_sync(0xffffffffu, p2, 1);
        p2 += __shfl_xor_sync(0xffffffffu, p2, 2);
        if (tg == 0) {
            sP[(m * 2 + nh) * QUAD_ROWS + m0 + gid]     = p1;
            sP[(m * 2 + nh) * QUAD_ROWS + m0 + 8 + gid] = p2;
        }
    }
    __syncthreads();

    if (tid < QUAD_ROWS) {
        float A = sP[0 * QUAD_ROWS + tid] + sP[1 * QUAD_ROWS + tid];
        float B = sP[2 * QUAD_ROWS + tid] + sP[3 * QUAD_ROWS + tid];
        float C = sP[4 * QUAD_ROWS + tid] + sP[5 * QUAD_ROWS + tid];
        sCos[tid] = C * rsqrtf(fmaxf(A * B, 1e-30f));
    }
    __syncthreads();
    if (tid == 0) {
        float s = 0.f;
#pragma unroll 8
        for (int i = 0; i < QUAD_ROWS; i++) s += sCos[i];
        g_loss_part[blockIdx.x] = s;
    }
}

// ============================================================================
// Kernel 4: final deterministic reduction + loss
//   loss = (2b - 2*sum_i cos_i) / b^2    (temperature cancels exactly)
// ============================================================================
__global__ void __launch_bounds__(QUAD_BLOCKS) final_kernel(float* __restrict__ out) {
    __shared__ float w[QUAD_BLOCKS / 32];
    int tid = threadIdx.x;
    float v = g_loss_part[tid];
#pragma unroll
    for (int off = 16; off > 0; off >>= 1)
        v += __shfl_xor_sync(0xffffffffu, v, off);
    if ((tid & 31) == 0) w[tid >> 5] = v;
    __syncthreads();
    if (tid == 0) {
        float s = 0.f;
#pragma unroll
        for (int i = 0; i < QUAD_BLOCKS / 32; i++) s += w[i];
        const float b = (float)BSZ;
        out[0] = (2.f * b - 2.f * s) / (b * b);
    }
}

// ============================================================================
extern "C" void kernel_launch(void* const* d_in, const int* in_sizes, int n_in,
                              void* d_out, int out_size) {
    (void)in_sizes; (void)n_in; (void)out_size;
    const float* zxs = (const float*)d_in[0];
    const float* zys = (const float*)d_in[1];
    const float* zxt = (const float*)d_in[2];
    const float* zyt = (const float*)d_in[3];
    // temperature (d_in[4]) cancels exactly under row-normalization.

    cudaFuncSetAttribute(gram_kernel, cudaFuncAttributeMaxDynamicSharedMemorySize,
                         GRAM_SMEM_BYTES);
    cudaFuncSetAttribute(quad_kernel, cudaFuncAttributeMaxDynamicSharedMemorySize,
                         QUAD_SMEM_BYTES);

    gram_kernel<<<GRAM_CTAS, 256, GRAM_SMEM_BYTES>>>(zys, zyt);
    reduce_gram_kernel<<<(3 * DIM * DIM) / 256, 256>>>();
    quad_kernel<<<QUAD_BLOCKS, 256, QUAD_SMEM_BYTES>>>(zxs, zxt);
    final_kernel<<<1, QUAD_BLOCKS>>>((float*)d_out);
}